// round 8
// baseline (speedup 1.0000x reference)
#include <cuda_runtime.h>
#include <cuda_bf16.h>
#include <math.h>
#include <stdint.h>

#define T   2048
#define Dm  512
#define Np  32
#define Hd  2048
#define Kk  4
#define NHd 8
#define HDd 64
#define Sd  1024
#define Bd  2
#define D3  1536

#define AT_PAD 68
#define AT_REG (64 * AT_PAD)
#define SMEM_ATTN (3 * AT_REG * 4)

// HMMA tile constants: pitch 72 bf16 per row, 128 rows per tile
#define FP 72
#define FTILE (128 * FP)                   // bf16 units per tile
#define STAGE_BYTES (2 * FTILE * 2)        // A+B tile bytes per stage
#define SMEM_FFN (3 * STAGE_BYTES)         // 3-stage ring

#define CP16(d, s) asm volatile("cp.async.cg.shared.global [%0], [%1], 16;" :: "r"(d), "l"(s))
#define CP_COMMIT() asm volatile("cp.async.commit_group;" ::: "memory")
#define CP_WAIT1() asm volatile("cp.async.wait_group 1;" ::: "memory")
#define CP_WAIT0() asm volatile("cp.async.wait_group 0;" ::: "memory")

__device__ int   g_idx[T * Kk];
__device__ int   g_cnt[Np];
__device__ int   g_list[Np * T];
__device__ float g_pairs[T * Kk * Dm];
__device__ float g_nout[T * Dm];
__device__ float g_qkv[T * D3];
__device__ float g_attno[T * Dm];
__device__ float g_attnout[T * Dm];
__device__ __nv_bfloat16 g_x3[T * 2 * Dm];                 // [t][hi(512)|lo(512)]
__device__ __nv_bfloat16 g_nout3[T * 2 * Dm];
__device__ __nv_bfloat16 g_attno3[T * 2 * Dm];
__device__ __nv_bfloat16 g_W13[(size_t)Np * Hd * 2 * Dm];  // [n][h][Wh|Wl]
__device__ __nv_bfloat16 g_W23[(size_t)Np * Dm * 2 * Hd];  // [n][d][Wh|Wl]
__device__ __nv_bfloat16 g_Wqkv3[(size_t)D3 * 2 * Dm];
__device__ __nv_bfloat16 g_Wo3[(size_t)Dm * 2 * Dm];
__device__ __nv_bfloat16 g_h3[(size_t)T * Kk * 2 * Hd];    // [pair][hh|hl]

__device__ __forceinline__ float gelu_f(float v) {
    float u = 0.7978845608028654f * (v + 0.044715f * v * v * v);
    return 0.5f * v * (1.0f + tanhf(u));
}

__device__ __forceinline__ uint32_t cvta_smem(const void* p) {
    uint32_t a;
    asm("{ .reg .u64 t; cvta.to.shared.u64 t, %1; cvt.u32.u64 %0, t; }" : "=r"(a) : "l"(p));
    return a;
}

__device__ __forceinline__ void mma_bf16(float c[4], uint32_t a0, uint32_t a1,
                                         uint32_t a2, uint32_t a3,
                                         uint32_t b0, uint32_t b1) {
    asm volatile(
        "mma.sync.aligned.m16n8k16.row.col.f32.bf16.bf16.f32 "
        "{%0,%1,%2,%3}, {%4,%5,%6,%7}, {%8,%9}, {%0,%1,%2,%3};"
        : "+f"(c[0]), "+f"(c[1]), "+f"(c[2]), "+f"(c[3])
        : "r"(a0), "r"(a1), "r"(a2), "r"(a3), "r"(b0), "r"(b1));
}

__device__ __forceinline__ void ldsm4(uint32_t r[4], uint32_t a) {
    asm volatile("ldmatrix.sync.aligned.m8n8.x4.shared.b16 {%0,%1,%2,%3}, [%4];"
        : "=r"(r[0]), "=r"(r[1]), "=r"(r[2]), "=r"(r[3]) : "r"(a));
}

// ---------------- router / list ----------------
__global__ void router_k(const float* __restrict__ x, const float* __restrict__ Wr,
                         const float* __restrict__ br) {
    int warp = threadIdx.x >> 5, lane = threadIdx.x & 31;
    int t = blockIdx.x * 8 + warp;
    const float* xp = x + (size_t)t * Dm + lane * 16;
    float4 xv[4];
#pragma unroll
    for (int i = 0; i < 4; i++) xv[i] = *(const float4*)(xp + i * 4);
    float lg[32];
#pragma unroll 1
    for (int n = 0; n < 32; n++) {
        const float* wp = Wr + n * Dm + lane * 16;
        float acc = 0.f;
#pragma unroll
        for (int i = 0; i < 4; i++) {
            float4 w = *(const float4*)(wp + i * 4);
            acc += xv[i].x * w.x + xv[i].y * w.y + xv[i].z * w.z + xv[i].w * w.w;
        }
#pragma unroll
        for (int o = 16; o; o >>= 1) acc += __shfl_xor_sync(0xffffffffu, acc, o);
        lg[n] = acc + br[n];
    }
    if (lane == 0) {
        unsigned used = 0;
        for (int k2 = 0; k2 < 4; k2++) {
            float best = -1e30f; int bi = 0;
            for (int n = 0; n < 32; n++)
                if (!((used >> n) & 1u) && lg[n] > best) { best = lg[n]; bi = n; }
            used |= 1u << bi;
            g_idx[t * 4 + k2] = bi;
        }
    }
}
__global__ void zero_k() { if (threadIdx.x < Np) g_cnt[threadIdx.x] = 0; }
__global__ void build_k() {
    int e = blockIdx.x * 256 + threadIdx.x;
    if (e >= T * Kk) return;
    int n = g_idx[e];
    int pos = atomicAdd(&g_cnt[n], 1);
    g_list[n * T + pos] = e;
}

// ---------------- bf16 split conversions ----------------
__global__ void conv3_k(const float* __restrict__ src, __nv_bfloat16* __restrict__ dst) {
    int i = blockIdx.x * 256 + threadIdx.x;
    int t = i >> 9, d = i & 511;
    float v = src[i];
    __nv_bfloat16 hi = __float2bfloat16(v);
    __nv_bfloat16 lo = __float2bfloat16(v - __bfloat162float(hi));
    dst[(size_t)t * 1024 + d] = hi;
    dst[(size_t)t * 1024 + 512 + d] = lo;
}
__global__ void convw_k(const float* __restrict__ W, __nv_bfloat16* __restrict__ W3,
                        int Kd, int Nd) {
    __shared__ float tile[32][33];
    int n = blockIdx.z, k0 = blockIdx.y * 32, c0 = blockIdx.x * 32;
    const float* Wn = W + (size_t)n * Kd * Nd;
#pragma unroll
    for (int i = 0; i < 32; i += 8)
        tile[threadIdx.y + i][threadIdx.x] = Wn[(size_t)(k0 + threadIdx.y + i) * Nd + c0 + threadIdx.x];
    __syncthreads();
    __nv_bfloat16* Wo = W3 + (size_t)n * Nd * 2 * Kd;
#pragma unroll
    for (int i = 0; i < 32; i += 8) {
        float v = tile[threadIdx.x][threadIdx.y + i];
        __nv_bfloat16 hi = __float2bfloat16(v);
        __nv_bfloat16 lo = __float2bfloat16(v - __bfloat162float(hi));
        size_t ro = (size_t)(c0 + threadIdx.y + i) * 2 * Kd + k0 + threadIdx.x;
        Wo[ro] = hi;
        Wo[ro + Kd] = lo;
    }
}
__global__ void convwd_k(const float* __restrict__ W, __nv_bfloat16* __restrict__ W3, int K) {
    int i = blockIdx.x * 256 + threadIdx.x;
    int n = i / K, k = i - n * K;
    float v = W[i];
    __nv_bfloat16 hi = __float2bfloat16(v);
    __nv_bfloat16 lo = __float2bfloat16(v - __bfloat162float(hi));
    W3[(size_t)n * 2 * K + k] = hi;
    W3[(size_t)n * 2 * K + K + k] = lo;
}

// ---------------- shared HMMA mainloop ----------------
__device__ __forceinline__ void hmma_chunk(uint32_t smb_bytes_A, uint32_t smb_bytes_B,
                                           int warpM, int warpN, int rA, int kA,
                                           int rB, int kB, float acc[4][4][4]) {
#pragma unroll
    for (int kk = 0; kk < 4; kk++) {
        uint32_t af[4][4], bf[4][2];
#pragma unroll
        for (int mt = 0; mt < 4; mt++)
            ldsm4(af[mt], smb_bytes_A + (uint32_t)(((warpM + mt * 16 + rA) * FP + kk * 16 + kA) * 2));
#pragma unroll
        for (int nt2 = 0; nt2 < 2; nt2++) {
            uint32_t treg[4];
            ldsm4(treg, smb_bytes_B + (uint32_t)(((warpN + nt2 * 16 + rB) * FP + kk * 16 + kB) * 2));
            bf[2 * nt2][0] = treg[0]; bf[2 * nt2][1] = treg[1];
            bf[2 * nt2 + 1][0] = treg[2]; bf[2 * nt2 + 1][1] = treg[3];
        }
#pragma unroll
        for (int mt = 0; mt < 4; mt++)
#pragma unroll
            for (int nt = 0; nt < 4; nt++)
                mma_bf16(acc[mt][nt], af[mt][0], af[mt][1], af[mt][2], af[mt][3],
                         bf[nt][0], bf[nt][1]);
    }
}

// ---------------- FFN pass 1: h = gelu(x @ W1 + b1) ----------------
__global__ __launch_bounds__(256, 2)
void ffn1_mma_k(const float* __restrict__ b1) {
    int n = blockIdx.z, mt0 = blockIdx.y, nb = blockIdx.x * 128;
    int cnt = g_cnt[n];
    int base = mt0 * 128;
    if (base >= cnt) return;

    extern __shared__ __align__(16) __nv_bfloat16 sm[];
    __shared__ int es[128];
    int tid = threadIdx.x, wid = tid >> 5, lane = tid & 31;
    if (tid < 128) es[tid] = (base + tid < cnt) ? g_list[n * T + base + tid] : -1;
    __syncthreads();

    int hr = tid >> 1, half = tid & 1;
    int e_row = es[hr];
    const __nv_bfloat16* arow = (e_row >= 0) ? (g_x3 + (size_t)(e_row >> 2) * 1024) : g_x3;
    const __nv_bfloat16* brow = g_W13 + ((size_t)n * Hd + nb + hr) * 1024;

    float acc[4][4][4];
#pragma unroll
    for (int i = 0; i < 4; i++)
#pragma unroll
        for (int j = 0; j < 4; j++)
#pragma unroll
            for (int k = 0; k < 4; k++) acc[i][j][k] = 0.f;

    int g = lane >> 2, t2 = (lane & 3) * 2;
    int warpM = (wid >> 2) * 64, warpN = (wid & 3) * 32;
    int rA = ((lane >> 3) & 1) * 8 + (lane & 7);
    int kA = (lane >> 4) * 8;
    int rB = (lane & 7) + (lane >> 4) * 8;
    int kB = ((lane >> 3) & 1) * 8;
    uint32_t smb = cvta_smem(sm);
    uint32_t dA0 = smb + (uint32_t)((hr * FP + half * 32) * 2);

    const int NCH = 24;
    auto issue = [&](int c1) {
        int kc = c1 & 7;
        int sA = (c1 < 16) ? 0 : 512;
        int sB = (c1 >= 8 && c1 < 16) ? 512 : 0;
        uint32_t st = (uint32_t)(c1 % 3) * STAGE_BYTES;
        const __nv_bfloat16* ap = arow + sA + kc * 64 + half * 32;
        const __nv_bfloat16* bp = brow + sB + kc * 64 + half * 32;
        uint32_t dA = dA0 + st, dB = dA + FTILE * 2;
#pragma unroll
        for (int i = 0; i < 4; i++) { CP16(dA + i * 16, ap + i * 8); CP16(dB + i * 16, bp + i * 8); }
        CP_COMMIT();
    };
    issue(0); issue(1);
#pragma unroll 1
    for (int c = 0; c < NCH; c++) {
        if (c + 2 < NCH) CP_WAIT1(); else CP_WAIT0();
        __syncthreads();
        if (c + 2 < NCH) issue(c + 2);
        uint32_t baseA = smb + (uint32_t)((c % 3) * STAGE_BYTES);
        hmma_chunk(baseA, baseA + FTILE * 2, warpM, warpN, rA, kA, rB, kB, acc);
    }

#pragma unroll
    for (int mt = 0; mt < 4; mt++) {
#pragma unroll
        for (int rr = 0; rr < 2; rr++) {
            int row = warpM + mt * 16 + g + rr * 8;
            int er = es[row];
            if (er < 0) continue;
            __nv_bfloat16* hp = g_h3 + (size_t)er * 4096;
#pragma unroll
            for (int nt = 0; nt < 4; nt++) {
                int col = nb + warpN + nt * 8 + t2;
                float v0 = gelu_f(acc[mt][nt][rr * 2 + 0] + b1[(size_t)n * Hd + col]);
                float v1 = gelu_f(acc[mt][nt][rr * 2 + 1] + b1[(size_t)n * Hd + col + 1]);
                __nv_bfloat16 h0 = __float2bfloat16(v0), h1 = __float2bfloat16(v1);
                __nv_bfloat16 l0 = __float2bfloat16(v0 - __bfloat162float(h0));
                __nv_bfloat16 l1 = __float2bfloat16(v1 - __bfloat162float(h1));
                uint32_t hp2 = (uint32_t)__bfloat16_as_ushort(h0) | ((uint32_t)__bfloat16_as_ushort(h1) << 16);
                uint32_t lp2 = (uint32_t)__bfloat16_as_ushort(l0) | ((uint32_t)__bfloat16_as_ushort(l1) << 16);
                *(uint32_t*)(hp + col) = hp2;
                *(uint32_t*)(hp + 2048 + col) = lp2;
            }
        }
    }
}

// ---------------- FFN pass 2: out = h @ W2 + b2 ----------------
__global__ __launch_bounds__(256, 2)
void ffn2_mma_k(const float* __restrict__ b2) {
    int n = blockIdx.z, mt0 = blockIdx.y, nb = blockIdx.x * 128;
    int cnt = g_cnt[n];
    int base = mt0 * 128;
    if (base >= cnt) return;

    extern __shared__ __align__(16) __nv_bfloat16 sm[];
    __shared__ int es[128];
    int tid = threadIdx.x, wid = tid >> 5, lane = tid & 31;
    if (tid < 128) es[tid] = (base + tid < cnt) ? g_list[n * T + base + tid] : -1;
    __syncthreads();

    int hr = tid >> 1, half = tid & 1;
    int e_row = es[hr];
    const __nv_bfloat16* arow = (e_row >= 0) ? (g_h3 + (size_t)e_row * 4096) : g_h3;
    const __nv_bfloat16* brow = g_W23 + ((size_t)n * Dm + nb + hr) * 4096;

    float acc[4][4][4];
#pragma unroll
    for (int i = 0; i < 4; i++)
#pragma unroll
        for (int j = 0; j < 4; j++)
#pragma unroll
            for (int k = 0; k < 4; k++) acc[i][j][k] = 0.f;

    int g = lane >> 2, t2 = (lane & 3) * 2;
    int warpM = (wid >> 2) * 64, warpN = (wid & 3) * 32;
    int rA = ((lane >> 3) & 1) * 8 + (lane & 7);
    int kA = (lane >> 4) * 8;
    int rB = (lane & 7) + (lane >> 4) * 8;
    int kB = ((lane >> 3) & 1) * 8;
    uint32_t smb = cvta_smem(sm);
    uint32_t dA0 = smb + (uint32_t)((hr * FP + half * 32) * 2);

    const int NCH = 96;
    auto issue = [&](int c1) {
        int kc = c1 & 31;
        int sA = (c1 < 64) ? 0 : 2048;
        int sB = (c1 >= 32 && c1 < 64) ? 2048 : 0;
        uint32_t st = (uint32_t)(c1 % 3) * STAGE_BYTES;
        const __nv_bfloat16* ap = arow + sA + kc * 64 + half * 32;
        const __nv_bfloat16* bp = brow + sB + kc * 64 + half * 32;
        uint32_t dA = dA0 + st, dB = dA + FTILE * 2;
#pragma unroll
        for (int i = 0; i < 4; i++) { CP16(dA + i * 16, ap + i * 8); CP16(dB + i * 16, bp + i * 8); }
        CP_COMMIT();
    };
    issue(0); issue(1);
#pragma unroll 1
    for (int c = 0; c < NCH; c++) {
        if (c + 2 < NCH) CP_WAIT1(); else CP_WAIT0();
        __syncthreads();
        if (c + 2 < NCH) issue(c + 2);
        uint32_t baseA = smb + (uint32_t)((c % 3) * STAGE_BYTES);
        hmma_chunk(baseA, baseA + FTILE * 2, warpM, warpN, rA, kA, rB, kB, acc);
    }

#pragma unroll
    for (int mt = 0; mt < 4; mt++) {
#pragma unroll
        for (int rr = 0; rr < 2; rr++) {
            int row = warpM + mt * 16 + g + rr * 8;
            int er = es[row];
            if (er < 0) continue;
            float* op = g_pairs + (size_t)er * Dm;
#pragma unroll
            for (int nt = 0; nt < 4; nt++) {
                int col = nb + warpN + nt * 8 + t2;
                float2 o;
                o.x = acc[mt][nt][rr * 2 + 0] + b2[(size_t)n * Dm + col];
                o.y = acc[mt][nt][rr * 2 + 1] + b2[(size_t)n * Dm + col + 1];
                *(float2*)(op + col) = o;
            }
        }
    }
}

// ---------------- dense HMMA GEMM: C[M,Nc] = A @ W^T + bias ----------------
__global__ __launch_bounds__(256, 2)
void gemm_mma_k(const __nv_bfloat16* __restrict__ A3, const __nv_bfloat16* __restrict__ W3,
                const float* __restrict__ bias, float* __restrict__ C, int Nc, int Kd) {
    int nb = blockIdx.x * 128, mg = blockIdx.y * 128;
    extern __shared__ __align__(16) __nv_bfloat16 sm[];
    int tid = threadIdx.x, wid = tid >> 5, lane = tid & 31;

    int hr = tid >> 1, half = tid & 1;
    const __nv_bfloat16* arow = A3 + (size_t)(mg + hr) * 2 * Kd;
    const __nv_bfloat16* brow = W3 + (size_t)(nb + hr) * 2 * Kd;

    float acc[4][4][4];
#pragma unroll
    for (int i = 0; i < 4; i++)
#pragma unroll
        for (int j = 0; j < 4; j++)
#pragma unroll
            for (int k = 0; k < 4; k++) acc[i][j][k] = 0.f;

    int g = lane >> 2, t2 = (lane & 3) * 2;
    int warpM = (wid >> 2) * 64, warpN = (wid & 3) * 32;
    int rA = ((lane >> 3) & 1) * 8 + (lane & 7);
    int kA = (lane >> 4) * 8;
    int rB = (lane & 7) + (lane >> 4) * 8;
    int kB = ((lane >> 3) & 1) * 8;
    uint32_t smb = cvta_smem(sm);
    uint32_t dA0 = smb + (uint32_t)((hr * FP + half * 32) * 2);

    int cpseg = Kd >> 6;
    int NCH = 3 * cpseg;
    auto issue = [&](int c1) {
        int seg = c1 / cpseg;
        int kc = c1 - seg * cpseg;
        int sA = (seg == 2) ? Kd : 0;
        int sB = (seg == 1) ? Kd : 0;
        uint32_t st = (uint32_t)(c1 % 3) * STAGE_BYTES;
        const __nv_bfloat16* ap = arow + sA + kc * 64 + half * 32;
        const __nv_bfloat16* bp = brow + sB + kc * 64 + half * 32;
        uint32_t dA = dA0 + st, dB = dA + FTILE * 2;
#pragma unroll
        for (int i = 0; i < 4; i++) { CP16(dA + i * 16, ap + i * 8); CP16(dB + i * 16, bp + i * 8); }
        CP_COMMIT();
    };
    issue(0); issue(1);
#pragma unroll 1
    for (int c = 0; c < NCH; c++) {
        if (c + 2 < NCH) CP_WAIT1(); else CP_WAIT0();
        __syncthreads();
        if (c + 2 < NCH) issue(c + 2);
        uint32_t baseA = smb + (uint32_t)((c % 3) * STAGE_BYTES);
        hmma_chunk(baseA, baseA + FTILE * 2, warpM, warpN, rA, kA, rB, kB, acc);
    }

#pragma unroll
    for (int mt = 0; mt < 4; mt++) {
#pragma unroll
        for (int rr = 0; rr < 2; rr++) {
            int row = mg + warpM + mt * 16 + g + rr * 8;
            float* op = C + (size_t)row * Nc;
#pragma unroll
            for (int nt = 0; nt < 4; nt++) {
                int col = nb + warpN + nt * 8 + t2;
                float2 o;
                o.x = acc[mt][nt][rr * 2 + 0] + bias[col];
                o.y = acc[mt][nt][rr * 2 + 1] + bias[col + 1];
                *(float2*)(op + col) = o;
            }
        }
    }
}

// ---------------- mean over k ----------------
__global__ void reduce_k() {
    int id = blockIdx.x * 256 + threadIdx.x;
    if (id >= T * Dm / 4) return;
    int t = id >> 7, c4 = (id & 127) << 2;
    float4 s = make_float4(0.f, 0.f, 0.f, 0.f);
#pragma unroll
    for (int k2 = 0; k2 < 4; k2++) {
        float4 v = *(const float4*)&g_pairs[(size_t)(t * 4 + k2) * Dm + c4];
        s.x += v.x; s.y += v.y; s.z += v.z; s.w += v.w;
    }
    s.x *= 0.25f; s.y *= 0.25f; s.z *= 0.25f; s.w *= 0.25f;
    *(float4*)&g_nout[(size_t)t * Dm + c4] = s;
}

// ---------------- attention (flash, q-tile 64) ----------------
__global__ __launch_bounds__(256)
void attn2_k() {
    extern __shared__ float smf[];
    float* Qs  = smf;
    float* KPs = smf + AT_REG;
    float* Vs  = smf + 2 * AT_REG;
    int q0 = blockIdx.x * 64, h = blockIdx.y, b = blockIdx.z;
    int tid = threadIdx.x, lane = tid & 31, w = tid >> 5;
    int qr = w * 8;
    {
        int r = tid >> 2, c0 = (tid & 3) * 16;
        const float* qp = g_qkv + (size_t)(b * Sd + q0 + r) * D3 + h * HDd + c0;
#pragma unroll
        for (int i = 0; i < 4; i++) {
            float4 v = *(const float4*)(qp + i * 4);
            Qs[(c0 + i * 4 + 0) * AT_PAD + r] = v.x * 0.125f;
            Qs[(c0 + i * 4 + 1) * AT_PAD + r] = v.y * 0.125f;
            Qs[(c0 + i * 4 + 2) * AT_PAD + r] = v.z * 0.125f;
            Qs[(c0 + i * 4 + 3) * AT_PAD + r] = v.w * 0.125f;
        }
    }
    float m[8], l[8], o0[8], o1[8];
#pragma unroll
    for (int r = 0; r < 8; r++) { m[r] = -1e30f; l[r] = 0.f; o0[r] = 0.f; o1[r] = 0.f; }
#pragma unroll 1
    for (int j0 = 0; j0 < Sd; j0 += 64) {
        __syncthreads();
        {
            int r = tid >> 2, c0 = (tid & 3) * 16;
            const float* kp = g_qkv + (size_t)(b * Sd + j0 + r) * D3 + Dm + h * HDd + c0;
            const float* vp = kp + Dm;
#pragma unroll
            for (int i = 0; i < 4; i++) {
                float4 kv = *(const float4*)(kp + i * 4);
                KPs[(c0 + i * 4 + 0) * AT_PAD + r] = kv.x;
                KPs[(c0 + i * 4 + 1) * AT_PAD + r] = kv.y;
                KPs[(c0 + i * 4 + 2) * AT_PAD + r] = kv.z;
                KPs[(c0 + i * 4 + 3) * AT_PAD + r] = kv.w;
                float4 vv = *(const float4*)(vp + i * 4);
                Vs[(c0 + i * 4 + 0) * AT_PAD + r] = vv.x;
                Vs[(c0 + i * 4 + 1) * AT_PAD + r] = vv.y;
                Vs[(c0 + i * 4 + 2) * AT_PAD + r] = vv.z;
                Vs[(c0 + i * 4 + 3) * AT_PAD + r] = vv.w;
            }
        }
        __syncthreads();
        float s[8][2];
#pragma unroll
        for (int r = 0; r < 8; r++) { s[r][0] = 0.f; s[r][1] = 0.f; }
#pragma unroll 8
        for (int d = 0; d < 64; d++) {
            float4 qa = *(const float4*)&Qs[d * AT_PAD + qr];
            float4 qb = *(const float4*)&Qs[d * AT_PAD + qr + 4];
            float2 kk = *(const float2*)&KPs[d * AT_PAD + 2 * lane];
            s[0][0] += qa.x * kk.x; s[0][1] += qa.x * kk.y;
            s[1][0] += qa.y * kk.x; s[1][1] += qa.y * kk.y;
            s[2][0] += qa.z * kk.x; s[2][1] += qa.z * kk.y;
            s[3][0] += qa.w * kk.x; s[3][1] += qa.w * kk.y;
            s[4][0] += qb.x * kk.x; s[4][1] += qb.x * kk.y;
            s[5][0] += qb.y * kk.x; s[5][1] += qb.y * kk.y;
            s[6][0] += qb.z * kk.x; s[6][1] += qb.z * kk.y;
            s[7][0] += qb.w * kk.x; s[7][1] += qb.w * kk.y;
        }
#pragma unroll
        for (int r = 0; r < 8; r++) {
            float tmax = fmaxf(s[r][0], s[r][1]);
#pragma unroll
            for (int o = 16; o; o >>= 1) tmax = fmaxf(tmax, __shfl_xor_sync(0xffffffffu, tmax, o));
            float mn = fmaxf(m[r], tmax);
            float corr = __expf(m[r] - mn);
            float p0 = __expf(s[r][0] - mn);
            float p1 = __expf(s[r][1] - mn);
            float rs = p0 + p1;
#pragma unroll
            for (int o = 16; o; o >>= 1) rs += __shfl_xor_sync(0xffffffffu, rs, o);
            l[r] = l[r] * corr + rs;
            m[r] = mn;
            o0[r] *= corr; o1[r] *= corr;
            s[r][0] = p0; s[r][1] = p1;
        }
        __syncthreads();
#pragma unroll
        for (int r = 0; r < 8; r++)
            *(float2*)&KPs[(qr + r) * AT_PAD + 2 * lane] = make_float2(s[r][0], s[r][1]);
        __syncthreads();
        const float* vr0 = &Vs[lane * AT_PAD];
        const float* vr1 = &Vs[(lane + 32) * AT_PAD];
#pragma unroll 4
        for (int k4 = 0; k4 < 16; k4++) {
            float4 v0 = *(const float4*)(vr0 + 4 * k4);
            float4 v1 = *(const float4*)(vr1 + 4 * k4);
#pragma unroll
            for (int r = 0; r < 8; r++) {
                float4 p = *(const float4*)&KPs[(qr + r) * AT_PAD + 4 * k4];
                o0[r] += p.x * v0.x + p.y * v0.y + p.z * v0.z + p.w * v0.w;
                o1[r] += p.x * v1.x + p.y * v1.y + p.z * v1.z + p.w * v1.w;
            }
        }
    }
#pragma unroll
    for (int r = 0; r < 8; r++) {
        float inv = 1.0f / l[r];
        int t = b * Sd + q0 + qr + r;
        g_attno[(size_t)t * Dm + h * HDd + lane] = o0[r] * inv;
        g_attno[(size_t)t * Dm + h * HDd + lane + 32] = o1[r] * inv;
    }
}

// ---------------- fused dual LN ----------------
__global__ void ln_k(const float* __restrict__ x,
                     const float* __restrict__ ln1w, const float* __restrict__ ln1b,
                     const float* __restrict__ ln2w, const float* __restrict__ ln2b,
                     float* __restrict__ out) {
    int t = blockIdx.x, tid = threadIdx.x;
    __shared__ float r1[8], r2[8];
    __shared__ float mu_s, rs_s;
    size_t off = (size_t)t * Dm;
    float a0 = x[off + tid] + g_attnout[off + tid];
    float a1 = x[off + 256 + tid] + g_attnout[off + 256 + tid];
    float s = a0 + a1, ss = a0 * a0 + a1 * a1;
#pragma unroll
    for (int o = 16; o; o >>= 1) {
        s += __shfl_xor_sync(0xffffffffu, s, o);
        ss += __shfl_xor_sync(0xffffffffu, ss, o);
    }
    if ((tid & 31) == 0) { r1[tid >> 5] = s; r2[tid >> 5] = ss; }
    __syncthreads();
    if (tid == 0) {
        float S = 0.f, SS = 0.f;
#pragma unroll
        for (int i = 0; i < 8; i++) { S += r1[i]; SS += r2[i]; }
        float mu = S * (1.0f / 512.0f);
        mu_s = mu;
        rs_s = rsqrtf(SS * (1.0f / 512.0f) - mu * mu + 1e-5f);
    }
    __syncthreads();
    float mu = mu_s, rs = rs_s;
    float z0 = (a0 - mu) * rs * ln1w[tid] + ln1b[tid] + g_nout[off + tid];
    float z1 = (a1 - mu) * rs * ln1w[256 + tid] + ln1b[256 + tid] + g_nout[off + 256 + tid];
    s = z0 + z1; ss = z0 * z0 + z1 * z1;
#pragma unroll
    for (int o = 16; o; o >>= 1) {
        s += __shfl_xor_sync(0xffffffffu, s, o);
        ss += __shfl_xor_sync(0xffffffffu, ss, o);
    }
    __syncthreads();
    if ((tid & 31) == 0) { r1[tid >> 5] = s; r2[tid >> 5] = ss; }
    __syncthreads();
    if (tid == 0) {
        float S = 0.f, SS = 0.f;
#pragma unroll
        for (int i = 0; i < 8; i++) { S += r1[i]; SS += r2[i]; }
        float mu2 = S * (1.0f / 512.0f);
        mu_s = mu2;
        rs_s = rsqrtf(SS * (1.0f / 512.0f) - mu2 * mu2 + 1e-5f);
    }
    __syncthreads();
    mu = mu_s; rs = rs_s;
    out[off + tid] = (z0 - mu) * rs * ln2w[tid] + ln2b[tid];
    out[off + 256 + tid] = (z1 - mu) * rs * ln2w[256 + tid] + ln2b[256 + tid];
}

// ---------------- launcher ----------------
extern "C" void kernel_launch(void* const* d_in, const int* in_sizes, int n_in,
                              void* d_out, int out_size) {
    const float* x    = (const float*)d_in[0];
    const float* Wr   = (const float*)d_in[1];
    const float* br   = (const float*)d_in[2];
    const float* W1   = (const float*)d_in[3];
    const float* b1   = (const float*)d_in[4];
    const float* W2   = (const float*)d_in[5];
    const float* b2   = (const float*)d_in[6];
    const float* Wqkv = (const float*)d_in[7];
    const float* bqkv = (const float*)d_in[8];
    const float* Wo   = (const float*)d_in[9];
    const float* bo   = (const float*)d_in[10];
    const float* ln1w = (const float*)d_in[11];
    const float* ln1b = (const float*)d_in[12];
    const float* ln2w = (const float*)d_in[13];
    const float* ln2b = (const float*)d_in[14];
    float* out = (float*)d_out;

    float *p_nout, *p_qkv, *p_attno, *p_attnout;
    __nv_bfloat16 *p_x3, *p_w13, *p_w23, *p_wqkv3, *p_wo3, *p_nout3, *p_attno3;
    cudaGetSymbolAddress((void**)&p_nout, g_nout);
    cudaGetSymbolAddress((void**)&p_qkv, g_qkv);
    cudaGetSymbolAddress((void**)&p_attno, g_attno);
    cudaGetSymbolAddress((void**)&p_attnout, g_attnout);
    cudaGetSymbolAddress((void**)&p_x3, g_x3);
    cudaGetSymbolAddress((void**)&p_w13, g_W13);
    cudaGetSymbolAddress((void**)&p_w23, g_W23);
    cudaGetSymbolAddress((void**)&p_wqkv3, g_Wqkv3);
    cudaGetSymbolAddress((void**)&p_wo3, g_Wo3);
    cudaGetSymbolAddress((void**)&p_nout3, g_nout3);
    cudaGetSymbolAddress((void**)&p_attno3, g_attno3);

    static int attr_set = 0;
    if (!attr_set) {
        cudaFuncSetAttribute(attn2_k, cudaFuncAttributeMaxDynamicSharedMemorySize, SMEM_ATTN);
        cudaFuncSetAttribute(ffn1_mma_k, cudaFuncAttributeMaxDynamicSharedMemorySize, SMEM_FFN);
        cudaFuncSetAttribute(ffn2_mma_k, cudaFuncAttributeMaxDynamicSharedMemorySize, SMEM_FFN);
        cudaFuncSetAttribute(gemm_mma_k, cudaFuncAttributeMaxDynamicSharedMemorySize, SMEM_FFN);
        attr_set = 1;
    }

    // router + list build
    router_k<<<T / 8, 256>>>(x, Wr, br);
    zero_k<<<1, 32>>>();
    build_k<<<(T * Kk + 255) / 256, 256>>>();

    // bf16 hi/lo splits
    conv3_k<<<T * Dm / 256, 256>>>(x, p_x3);
    convw_k<<<dim3(Hd / 32, Dm / 32, Np), dim3(32, 8)>>>(W1, p_w13, Dm, Hd);
    convw_k<<<dim3(Dm / 32, Hd / 32, Np), dim3(32, 8)>>>(W2, p_w23, Hd, Dm);
    convwd_k<<<D3 * Dm / 256, 256>>>(Wqkv, p_wqkv3, Dm);
    convwd_k<<<Dm * Dm / 256, 256>>>(Wo, p_wo3, Dm);

    // sparse FFN on tensor cores (cp.async 3-stage pipeline)
    ffn1_mma_k<<<dim3(16, 16, 32), 256, SMEM_FFN>>>(b1);
    ffn2_mma_k<<<dim3(4, 16, 32), 256, SMEM_FFN>>>(b2);
    reduce_k<<<(T * Dm / 4 + 255) / 256, 256>>>();
    conv3_k<<<T * Dm / 256, 256>>>(p_nout, p_nout3);

    // attention (HMMA projections + fp32 flash core)
    gemm_mma_k<<<dim3(D3 / 128, T / 128), 256, SMEM_FFN>>>(p_nout3, p_wqkv3, bqkv, p_qkv, D3, Dm);
    attn2_k<<<dim3(Sd / 64, NHd, Bd), 256, SMEM_ATTN>>>();
    conv3_k<<<T * Dm / 256, 256>>>(p_attno, p_attno3);
    gemm_mma_k<<<dim3(Dm / 128, T / 128), 256, SMEM_FFN>>>(p_attno3, p_wo3, bo, p_attnout, Dm, Dm);

    // epilogue
    ln_k<<<T, 256>>>(x, ln1w, ln1b, ln2w, ln2b, out);
}

// round 9
// speedup vs baseline: 1.5617x; 1.5617x over previous
#include <cuda_runtime.h>
#include <cuda_bf16.h>
#include <math.h>
#include <stdint.h>

#define T   2048
#define Dm  512
#define Np  32
#define Hd  2048
#define Kk  4
#define NHd 8
#define HDd 64
#define Sd  1024
#define Bd  2
#define D3  1536

#define AT_PAD 68
#define AT_REG (64 * AT_PAD)
#define SMEM_ATTN (3 * AT_REG * 4)

// HMMA tile constants: pitch 72 bf16 per row, 128 rows per tile
#define FP 72
#define FTILE (128 * FP)               // bf16 units per tile
#define SMEM_FFN (4 * FTILE * 2)       // bytes: 2 bufs x (A + B)

__device__ int   g_idx[T * Kk];
__device__ int   g_cnt[Np];
__device__ int   g_list[Np * T];
__device__ float g_pairs[T * Kk * Dm];
__device__ float g_nout[T * Dm];
__device__ float g_qkv[T * D3];
__device__ float g_attnout[T * Dm];
__device__ __nv_bfloat16 g_x3[T * 2 * Dm];                 // [t][hi(512)|lo(512)]
__device__ __nv_bfloat16 g_nout3[T * 2 * Dm];
__device__ __nv_bfloat16 g_attno3[T * 2 * Dm];
__device__ __nv_bfloat16 g_W13[(size_t)Np * Hd * 2 * Dm];  // [n][h][Wh|Wl]
__device__ __nv_bfloat16 g_W23[(size_t)Np * Dm * 2 * Hd];  // [n][d][Wh|Wl]
__device__ __nv_bfloat16 g_Wqkv3[(size_t)D3 * 2 * Dm];
__device__ __nv_bfloat16 g_Wo3[(size_t)Dm * 2 * Dm];
__device__ __nv_bfloat16 g_h3[(size_t)T * Kk * 2 * Hd];    // [pair][hh|hl]

__device__ __forceinline__ float gelu_f(float v) {
    float u = 0.7978845608028654f * (v + 0.044715f * v * v * v);
    return 0.5f * v * (1.0f + tanhf(u));
}

__device__ __forceinline__ uint32_t cvta_smem(const void* p) {
    uint32_t a;
    asm("{ .reg .u64 t; cvta.to.shared.u64 t, %1; cvt.u32.u64 %0, t; }" : "=r"(a) : "l"(p));
    return a;
}

__device__ __forceinline__ void mma_bf16(float c[4], uint32_t a0, uint32_t a1,
                                         uint32_t a2, uint32_t a3,
                                         uint32_t b0, uint32_t b1) {
    asm volatile(
        "mma.sync.aligned.m16n8k16.row.col.f32.bf16.bf16.f32 "
        "{%0,%1,%2,%3}, {%4,%5,%6,%7}, {%8,%9}, {%0,%1,%2,%3};"
        : "+f"(c[0]), "+f"(c[1]), "+f"(c[2]), "+f"(c[3])
        : "r"(a0), "r"(a1), "r"(a2), "r"(a3), "r"(b0), "r"(b1));
}

__device__ __forceinline__ void ldsm4(uint32_t r[4], uint32_t a) {
    asm volatile("ldmatrix.sync.aligned.m8n8.x4.shared.b16 {%0,%1,%2,%3}, [%4];"
        : "=r"(r[0]), "=r"(r[1]), "=r"(r[2]), "=r"(r[3]) : "r"(a));
}

// ---------------- router / list ----------------
__global__ void router_k(const float* __restrict__ x, const float* __restrict__ Wr,
                         const float* __restrict__ br) {
    int warp = threadIdx.x >> 5, lane = threadIdx.x & 31;
    int t = blockIdx.x * 8 + warp;
    const float* xp = x + (size_t)t * Dm + lane * 16;
    float4 xv[4];
#pragma unroll
    for (int i = 0; i < 4; i++) xv[i] = *(const float4*)(xp + i * 4);
    float lg[32];
#pragma unroll 1
    for (int n = 0; n < 32; n++) {
        const float* wp = Wr + n * Dm + lane * 16;
        float acc = 0.f;
#pragma unroll
        for (int i = 0; i < 4; i++) {
            float4 w = *(const float4*)(wp + i * 4);
            acc += xv[i].x * w.x + xv[i].y * w.y + xv[i].z * w.z + xv[i].w * w.w;
        }
#pragma unroll
        for (int o = 16; o; o >>= 1) acc += __shfl_xor_sync(0xffffffffu, acc, o);
        lg[n] = acc + br[n];
    }
    if (lane == 0) {
        unsigned used = 0;
        for (int k2 = 0; k2 < 4; k2++) {
            float best = -1e30f; int bi = 0;
            for (int n = 0; n < 32; n++)
                if (!((used >> n) & 1u) && lg[n] > best) { best = lg[n]; bi = n; }
            used |= 1u << bi;
            g_idx[t * 4 + k2] = bi;
        }
    }
}
__global__ void zero_k() { if (threadIdx.x < Np) g_cnt[threadIdx.x] = 0; }
__global__ void build_k() {
    int e = blockIdx.x * 256 + threadIdx.x;
    if (e >= T * Kk) return;
    int n = g_idx[e];
    int pos = atomicAdd(&g_cnt[n], 1);
    g_list[n * T + pos] = e;
}

// ---------------- bf16 split conversions ----------------
__global__ void conv3_k(const float* __restrict__ src, __nv_bfloat16* __restrict__ dst) {
    int i = blockIdx.x * 256 + threadIdx.x;
    int t = i >> 9, d = i & 511;
    float v = src[i];
    __nv_bfloat16 hi = __float2bfloat16(v);
    __nv_bfloat16 lo = __float2bfloat16(v - __bfloat162float(hi));
    dst[(size_t)t * 1024 + d] = hi;
    dst[(size_t)t * 1024 + 512 + d] = lo;
}
__global__ void convw_k(const float* __restrict__ W, __nv_bfloat16* __restrict__ W3,
                        int Kd, int Nd) {
    __shared__ float tile[32][33];
    int n = blockIdx.z, k0 = blockIdx.y * 32, c0 = blockIdx.x * 32;
    const float* Wn = W + (size_t)n * Kd * Nd;
#pragma unroll
    for (int i = 0; i < 32; i += 8)
        tile[threadIdx.y + i][threadIdx.x] = Wn[(size_t)(k0 + threadIdx.y + i) * Nd + c0 + threadIdx.x];
    __syncthreads();
    __nv_bfloat16* Wo = W3 + (size_t)n * Nd * 2 * Kd;
#pragma unroll
    for (int i = 0; i < 32; i += 8) {
        float v = tile[threadIdx.x][threadIdx.y + i];
        __nv_bfloat16 hi = __float2bfloat16(v);
        __nv_bfloat16 lo = __float2bfloat16(v - __bfloat162float(hi));
        size_t ro = (size_t)(c0 + threadIdx.y + i) * 2 * Kd + k0 + threadIdx.x;
        Wo[ro] = hi;
        Wo[ro + Kd] = lo;
    }
}
__global__ void convwd_k(const float* __restrict__ W, __nv_bfloat16* __restrict__ W3, int K) {
    int i = blockIdx.x * 256 + threadIdx.x;
    int n = i / K, k = i - n * K;
    float v = W[i];
    __nv_bfloat16 hi = __float2bfloat16(v);
    __nv_bfloat16 lo = __float2bfloat16(v - __bfloat162float(hi));
    W3[(size_t)n * 2 * K + k] = hi;
    W3[(size_t)n * 2 * K + K + k] = lo;
}

// ---------------- shared HMMA mainloop ----------------
__device__ __forceinline__ void hmma_chunk(uint32_t smb_bytes_A, uint32_t smb_bytes_B,
                                           int warpM, int warpN, int rA, int kA,
                                           int rB, int kB, float acc[4][4][4]) {
#pragma unroll
    for (int kk = 0; kk < 4; kk++) {
        uint32_t af[4][4], bf[4][2];
#pragma unroll
        for (int mt = 0; mt < 4; mt++)
            ldsm4(af[mt], smb_bytes_A + (uint32_t)(((warpM + mt * 16 + rA) * FP + kk * 16 + kA) * 2));
#pragma unroll
        for (int nt2 = 0; nt2 < 2; nt2++) {
            uint32_t treg[4];
            ldsm4(treg, smb_bytes_B + (uint32_t)(((warpN + nt2 * 16 + rB) * FP + kk * 16 + kB) * 2));
            bf[2 * nt2][0] = treg[0]; bf[2 * nt2][1] = treg[1];
            bf[2 * nt2 + 1][0] = treg[2]; bf[2 * nt2 + 1][1] = treg[3];
        }
#pragma unroll
        for (int mt = 0; mt < 4; mt++)
#pragma unroll
            for (int nt = 0; nt < 4; nt++)
                mma_bf16(acc[mt][nt], af[mt][0], af[mt][1], af[mt][2], af[mt][3],
                         bf[nt][0], bf[nt][1]);
    }
}

// ---------------- FFN pass 1: h = gelu(x @ W1 + b1) ----------------
__global__ __launch_bounds__(256)
void ffn1_mma_k(const float* __restrict__ b1) {
    int n = blockIdx.z, mt0 = blockIdx.y, nb = blockIdx.x * 128;
    int cnt = g_cnt[n];
    int base = mt0 * 128;
    if (base >= cnt) return;

    extern __shared__ __align__(16) __nv_bfloat16 sm[];
    __shared__ int es[128];
    int tid = threadIdx.x, wid = tid >> 5, lane = tid & 31;
    if (tid < 128) es[tid] = (base + tid < cnt) ? g_list[n * T + base + tid] : -1;
    __syncthreads();

    int hr = tid >> 1, half = tid & 1;
    int e_row = es[hr];
    const __nv_bfloat16* arow = (e_row >= 0) ? (g_x3 + (size_t)(e_row >> 2) * 1024) : 0;
    const __nv_bfloat16* brow = g_W13 + ((size_t)n * Hd + nb + hr) * 1024;
    int sto = hr * FP + half * 32;

    float acc[4][4][4];
#pragma unroll
    for (int i = 0; i < 4; i++)
#pragma unroll
        for (int j = 0; j < 4; j++)
#pragma unroll
            for (int k = 0; k < 4; k++) acc[i][j][k] = 0.f;

    int g = lane >> 2, t2 = (lane & 3) * 2;
    int warpM = (wid >> 2) * 64, warpN = (wid & 3) * 32;
    int rA = ((lane >> 3) & 1) * 8 + (lane & 7);
    int kA = (lane >> 4) * 8;
    int rB = (lane & 7) + (lane >> 4) * 8;
    int kB = ((lane >> 3) & 1) * 8;
    uint32_t smb = cvta_smem(sm);

    const int NCH = 24;
    uint4 ra[4], rb[4];
    if (arow) {
#pragma unroll
        for (int i = 0; i < 4; i++) ra[i] = *(const uint4*)(arow + half * 32 + i * 8);
    } else {
#pragma unroll
        for (int i = 0; i < 4; i++) ra[i] = make_uint4(0, 0, 0, 0);
    }
#pragma unroll
    for (int i = 0; i < 4; i++) rb[i] = *(const uint4*)(brow + half * 32 + i * 8);
#pragma unroll
    for (int i = 0; i < 4; i++) {
        *(uint4*)(sm + sto + i * 8) = ra[i];
        *(uint4*)(sm + FTILE + sto + i * 8) = rb[i];
    }
    __syncthreads();

#pragma unroll 1
    for (int c = 0; c < NCH; c++) {
        int buf = c & 1;
        if (c + 1 < NCH) {
            int c1 = c + 1;
            int kc = c1 & 7;
            int sA = (c1 < 16) ? 0 : 512;
            int sB = (c1 >= 8 && c1 < 16) ? 512 : 0;
            if (arow) {
                const __nv_bfloat16* ap = arow + sA + kc * 64 + half * 32;
#pragma unroll
                for (int i = 0; i < 4; i++) ra[i] = *(const uint4*)(ap + i * 8);
            }
            const __nv_bfloat16* bp = brow + sB + kc * 64 + half * 32;
#pragma unroll
            for (int i = 0; i < 4; i++) rb[i] = *(const uint4*)(bp + i * 8);
        }
        uint32_t baseA = smb + (uint32_t)(buf * 2 * FTILE * 2);
        hmma_chunk(baseA, baseA + FTILE * 2, warpM, warpN, rA, kA, rB, kB, acc);
        if (c + 1 < NCH) {
            __nv_bfloat16* d = sm + ((c + 1) & 1) * 2 * FTILE;
#pragma unroll
            for (int i = 0; i < 4; i++) {
                *(uint4*)(d + sto + i * 8) = ra[i];
                *(uint4*)(d + FTILE + sto + i * 8) = rb[i];
            }
        }
        __syncthreads();
    }

#pragma unroll
    for (int mt = 0; mt < 4; mt++) {
#pragma unroll
        for (int rr = 0; rr < 2; rr++) {
            int row = warpM + mt * 16 + g + rr * 8;
            int er = es[row];
            if (er < 0) continue;
            __nv_bfloat16* hp = g_h3 + (size_t)er * 4096;
#pragma unroll
            for (int nt = 0; nt < 4; nt++) {
                int col = nb + warpN + nt * 8 + t2;
                float v0 = gelu_f(acc[mt][nt][rr * 2 + 0] + b1[(size_t)n * Hd + col]);
                float v1 = gelu_f(acc[mt][nt][rr * 2 + 1] + b1[(size_t)n * Hd + col + 1]);
                __nv_bfloat16 h0 = __float2bfloat16(v0), h1 = __float2bfloat16(v1);
                __nv_bfloat16 l0 = __float2bfloat16(v0 - __bfloat162float(h0));
                __nv_bfloat16 l1 = __float2bfloat16(v1 - __bfloat162float(h1));
                uint32_t hp2 = (uint32_t)__bfloat16_as_ushort(h0) | ((uint32_t)__bfloat16_as_ushort(h1) << 16);
                uint32_t lp2 = (uint32_t)__bfloat16_as_ushort(l0) | ((uint32_t)__bfloat16_as_ushort(l1) << 16);
                *(uint32_t*)(hp + col) = hp2;
                *(uint32_t*)(hp + 2048 + col) = lp2;
            }
        }
    }
}

// ---------------- FFN pass 2: out = h @ W2 + b2 ----------------
__global__ __launch_bounds__(256)
void ffn2_mma_k(const float* __restrict__ b2) {
    int n = blockIdx.z, mt0 = blockIdx.y, nb = blockIdx.x * 128;
    int cnt = g_cnt[n];
    int base = mt0 * 128;
    if (base >= cnt) return;

    extern __shared__ __align__(16) __nv_bfloat16 sm[];
    __shared__ int es[128];
    int tid = threadIdx.x, wid = tid >> 5, lane = tid & 31;
    if (tid < 128) es[tid] = (base + tid < cnt) ? g_list[n * T + base + tid] : -1;
    __syncthreads();

    int hr = tid >> 1, half = tid & 1;
    int e_row = es[hr];
    const __nv_bfloat16* arow = (e_row >= 0) ? (g_h3 + (size_t)e_row * 4096) : 0;
    const __nv_bfloat16* brow = g_W23 + ((size_t)n * Dm + nb + hr) * 4096;
    int sto = hr * FP + half * 32;

    float acc[4][4][4];
#pragma unroll
    for (int i = 0; i < 4; i++)
#pragma unroll
        for (int j = 0; j < 4; j++)
#pragma unroll
            for (int k = 0; k < 4; k++) acc[i][j][k] = 0.f;

    int g = lane >> 2, t2 = (lane & 3) * 2;
    int warpM = (wid >> 2) * 64, warpN = (wid & 3) * 32;
    int rA = ((lane >> 3) & 1) * 8 + (lane & 7);
    int kA = (lane >> 4) * 8;
    int rB = (lane & 7) + (lane >> 4) * 8;
    int kB = ((lane >> 3) & 1) * 8;
    uint32_t smb = cvta_smem(sm);

    const int NCH = 96;
    uint4 ra[4], rb[4];
    if (arow) {
#pragma unroll
        for (int i = 0; i < 4; i++) ra[i] = *(const uint4*)(arow + half * 32 + i * 8);
    } else {
#pragma unroll
        for (int i = 0; i < 4; i++) ra[i] = make_uint4(0, 0, 0, 0);
    }
#pragma unroll
    for (int i = 0; i < 4; i++) rb[i] = *(const uint4*)(brow + half * 32 + i * 8);
#pragma unroll
    for (int i = 0; i < 4; i++) {
        *(uint4*)(sm + sto + i * 8) = ra[i];
        *(uint4*)(sm + FTILE + sto + i * 8) = rb[i];
    }
    __syncthreads();

#pragma unroll 1
    for (int c = 0; c < NCH; c++) {
        int buf = c & 1;
        if (c + 1 < NCH) {
            int c1 = c + 1;
            int kc = c1 & 31;
            int sA = (c1 < 64) ? 0 : 2048;
            int sB = (c1 >= 32 && c1 < 64) ? 2048 : 0;
            if (arow) {
                const __nv_bfloat16* ap = arow + sA + kc * 64 + half * 32;
#pragma unroll
                for (int i = 0; i < 4; i++) ra[i] = *(const uint4*)(ap + i * 8);
            }
            const __nv_bfloat16* bp = brow + sB + kc * 64 + half * 32;
#pragma unroll
            for (int i = 0; i < 4; i++) rb[i] = *(const uint4*)(bp + i * 8);
        }
        uint32_t baseA = smb + (uint32_t)(buf * 2 * FTILE * 2);
        hmma_chunk(baseA, baseA + FTILE * 2, warpM, warpN, rA, kA, rB, kB, acc);
        if (c + 1 < NCH) {
            __nv_bfloat16* d = sm + ((c + 1) & 1) * 2 * FTILE;
#pragma unroll
            for (int i = 0; i < 4; i++) {
                *(uint4*)(d + sto + i * 8) = ra[i];
                *(uint4*)(d + FTILE + sto + i * 8) = rb[i];
            }
        }
        __syncthreads();
    }

#pragma unroll
    for (int mt = 0; mt < 4; mt++) {
#pragma unroll
        for (int rr = 0; rr < 2; rr++) {
            int row = warpM + mt * 16 + g + rr * 8;
            int er = es[row];
            if (er < 0) continue;
            float* op = g_pairs + (size_t)er * Dm;
#pragma unroll
            for (int nt = 0; nt < 4; nt++) {
                int col = nb + warpN + nt * 8 + t2;
                float2 o;
                o.x = acc[mt][nt][rr * 2 + 0] + b2[(size_t)n * Dm + col];
                o.y = acc[mt][nt][rr * 2 + 1] + b2[(size_t)n * Dm + col + 1];
                *(float2*)(op + col) = o;
            }
        }
    }
}

// ---------------- dense HMMA GEMM: C[M,Nc] = A @ W^T + bias ----------------
__global__ __launch_bounds__(256)
void gemm_mma_k(const __nv_bfloat16* __restrict__ A3, const __nv_bfloat16* __restrict__ W3,
                const float* __restrict__ bias, float* __restrict__ C, int Nc, int Kd) {
    int nb = blockIdx.x * 128, mg = blockIdx.y * 128;
    extern __shared__ __align__(16) __nv_bfloat16 sm[];
    int tid = threadIdx.x, wid = tid >> 5, lane = tid & 31;

    int hr = tid >> 1, half = tid & 1;
    const __nv_bfloat16* arow = A3 + (size_t)(mg + hr) * 2 * Kd;
    const __nv_bfloat16* brow = W3 + (size_t)(nb + hr) * 2 * Kd;
    int sto = hr * FP + half * 32;

    float acc[4][4][4];
#pragma unroll
    for (int i = 0; i < 4; i++)
#pragma unroll
        for (int j = 0; j < 4; j++)
#pragma unroll
            for (int k = 0; k < 4; k++) acc[i][j][k] = 0.f;

    int g = lane >> 2, t2 = (lane & 3) * 2;
    int warpM = (wid >> 2) * 64, warpN = (wid & 3) * 32;
    int rA = ((lane >> 3) & 1) * 8 + (lane & 7);
    int kA = (lane >> 4) * 8;
    int rB = (lane & 7) + (lane >> 4) * 8;
    int kB = ((lane >> 3) & 1) * 8;
    uint32_t smb = cvta_smem(sm);

    int cpseg = Kd >> 6;
    int NCH = 3 * cpseg;
    uint4 ra[4], rb[4];
#pragma unroll
    for (int i = 0; i < 4; i++) {
        ra[i] = *(const uint4*)(arow + half * 32 + i * 8);
        rb[i] = *(const uint4*)(brow + half * 32 + i * 8);
    }
#pragma unroll
    for (int i = 0; i < 4; i++) {
        *(uint4*)(sm + sto + i * 8) = ra[i];
        *(uint4*)(sm + FTILE + sto + i * 8) = rb[i];
    }
    __syncthreads();

#pragma unroll 1
    for (int c = 0; c < NCH; c++) {
        int buf = c & 1;
        if (c + 1 < NCH) {
            int c1 = c + 1;
            int seg = c1 / cpseg;
            int kc = c1 - seg * cpseg;
            int sA = (seg == 2) ? Kd : 0;
            int sB = (seg == 1) ? Kd : 0;
            const __nv_bfloat16* ap = arow + sA + kc * 64 + half * 32;
            const __nv_bfloat16* bp = brow + sB + kc * 64 + half * 32;
#pragma unroll
            for (int i = 0; i < 4; i++) {
                ra[i] = *(const uint4*)(ap + i * 8);
                rb[i] = *(const uint4*)(bp + i * 8);
            }
        }
        uint32_t baseA = smb + (uint32_t)(buf * 2 * FTILE * 2);
        hmma_chunk(baseA, baseA + FTILE * 2, warpM, warpN, rA, kA, rB, kB, acc);
        if (c + 1 < NCH) {
            __nv_bfloat16* d = sm + ((c + 1) & 1) * 2 * FTILE;
#pragma unroll
            for (int i = 0; i < 4; i++) {
                *(uint4*)(d + sto + i * 8) = ra[i];
                *(uint4*)(d + FTILE + sto + i * 8) = rb[i];
            }
        }
        __syncthreads();
    }

#pragma unroll
    for (int mt = 0; mt < 4; mt++) {
#pragma unroll
        for (int rr = 0; rr < 2; rr++) {
            int row = mg + warpM + mt * 16 + g + rr * 8;
            float* op = C + (size_t)row * Nc;
#pragma unroll
            for (int nt = 0; nt < 4; nt++) {
                int col = nb + warpN + nt * 8 + t2;
                float2 o;
                o.x = acc[mt][nt][rr * 2 + 0] + bias[col];
                o.y = acc[mt][nt][rr * 2 + 1] + bias[col + 1];
                *(float2*)(op + col) = o;
            }
        }
    }
}

// ---------------- mean over k, fused bf16 split ----------------
__global__ void reduce3_k() {
    int id = blockIdx.x * 256 + threadIdx.x;
    if (id >= T * Dm / 4) return;
    int t = id >> 7, c4 = (id & 127) << 2;
    float4 s = make_float4(0.f, 0.f, 0.f, 0.f);
#pragma unroll
    for (int k2 = 0; k2 < 4; k2++) {
        float4 v = *(const float4*)&g_pairs[(size_t)(t * 4 + k2) * Dm + c4];
        s.x += v.x; s.y += v.y; s.z += v.z; s.w += v.w;
    }
    s.x *= 0.25f; s.y *= 0.25f; s.z *= 0.25f; s.w *= 0.25f;
    *(float4*)&g_nout[(size_t)t * Dm + c4] = s;
    // bf16 hi/lo split
    float vv[4] = {s.x, s.y, s.z, s.w};
    ushort hi4[4], lo4[4];
#pragma unroll
    for (int i = 0; i < 4; i++) {
        __nv_bfloat16 hi = __float2bfloat16(vv[i]);
        __nv_bfloat16 lo = __float2bfloat16(vv[i] - __bfloat162float(hi));
        hi4[i] = __bfloat16_as_ushort(hi);
        lo4[i] = __bfloat16_as_ushort(lo);
    }
    *(uint2*)&g_nout3[(size_t)t * 1024 + c4] = *(uint2*)hi4;
    *(uint2*)&g_nout3[(size_t)t * 1024 + 512 + c4] = *(uint2*)lo4;
}

// ---------------- attention (flash, q-tile 64), bf16-split epilogue ----------------
__global__ __launch_bounds__(256)
void attn2_k() {
    extern __shared__ float smf[];
    float* Qs  = smf;
    float* KPs = smf + AT_REG;
    float* Vs  = smf + 2 * AT_REG;
    int q0 = blockIdx.x * 64, h = blockIdx.y, b = blockIdx.z;
    int tid = threadIdx.x, lane = tid & 31, w = tid >> 5;
    int qr = w * 8;
    {
        int r = tid >> 2, c0 = (tid & 3) * 16;
        const float* qp = g_qkv + (size_t)(b * Sd + q0 + r) * D3 + h * HDd + c0;
#pragma unroll
        for (int i = 0; i < 4; i++) {
            float4 v = *(const float4*)(qp + i * 4);
            Qs[(c0 + i * 4 + 0) * AT_PAD + r] = v.x * 0.125f;
            Qs[(c0 + i * 4 + 1) * AT_PAD + r] = v.y * 0.125f;
            Qs[(c0 + i * 4 + 2) * AT_PAD + r] = v.z * 0.125f;
            Qs[(c0 + i * 4 + 3) * AT_PAD + r] = v.w * 0.125f;
        }
    }
    float m[8], l[8], o0[8], o1[8];
#pragma unroll
    for (int r = 0; r < 8; r++) { m[r] = -1e30f; l[r] = 0.f; o0[r] = 0.f; o1[r] = 0.f; }
#pragma unroll 1
    for (int j0 = 0; j0 < Sd; j0 += 64) {
        __syncthreads();
        {
            int r = tid >> 2, c0 = (tid & 3) * 16;
            const float* kp = g_qkv + (size_t)(b * Sd + j0 + r) * D3 + Dm + h * HDd + c0;
            const float* vp = kp + Dm;
#pragma unroll
            for (int i = 0; i < 4; i++) {
                float4 kv = *(const float4*)(kp + i * 4);
                KPs[(c0 + i * 4 + 0) * AT_PAD + r] = kv.x;
                KPs[(c0 + i * 4 + 1) * AT_PAD + r] = kv.y;
                KPs[(c0 + i * 4 + 2) * AT_PAD + r] = kv.z;
                KPs[(c0 + i * 4 + 3) * AT_PAD + r] = kv.w;
                float4 vv = *(const float4*)(vp + i * 4);
                Vs[(c0 + i * 4 + 0) * AT_PAD + r] = vv.x;
                Vs[(c0 + i * 4 + 1) * AT_PAD + r] = vv.y;
                Vs[(c0 + i * 4 + 2) * AT_PAD + r] = vv.z;
                Vs[(c0 + i * 4 + 3) * AT_PAD + r] = vv.w;
            }
        }
        __syncthreads();
        float s[8][2];
#pragma unroll
        for (int r = 0; r < 8; r++) { s[r][0] = 0.f; s[r][1] = 0.f; }
#pragma unroll 8
        for (int d = 0; d < 64; d++) {
            float4 qa = *(const float4*)&Qs[d * AT_PAD + qr];
            float4 qb = *(const float4*)&Qs[d * AT_PAD + qr + 4];
            float2 kk = *(const float2*)&KPs[d * AT_PAD + 2 * lane];
            s[0][0] += qa.x * kk.x; s[0][1] += qa.x * kk.y;
            s[1][0] += qa.y * kk.x; s[1][1] += qa.y * kk.y;
            s[2][0] += qa.z * kk.x; s[2][1] += qa.z * kk.y;
            s[3][0] += qa.w * kk.x; s[3][1] += qa.w * kk.y;
            s[4][0] += qb.x * kk.x; s[4][1] += qb.x * kk.y;
            s[5][0] += qb.y * kk.x; s[5][1] += qb.y * kk.y;
            s[6][0] += qb.z * kk.x; s[6][1] += qb.z * kk.y;
            s[7][0] += qb.w * kk.x; s[7][1] += qb.w * kk.y;
        }
#pragma unroll
        for (int r = 0; r < 8; r++) {
            float tmax = fmaxf(s[r][0], s[r][1]);
#pragma unroll
            for (int o = 16; o; o >>= 1) tmax = fmaxf(tmax, __shfl_xor_sync(0xffffffffu, tmax, o));
            float mn = fmaxf(m[r], tmax);
            float corr = __expf(m[r] - mn);
            float p0 = __expf(s[r][0] - mn);
            float p1 = __expf(s[r][1] - mn);
            float rs = p0 + p1;
#pragma unroll
            for (int o = 16; o; o >>= 1) rs += __shfl_xor_sync(0xffffffffu, rs, o);
            l[r] = l[r] * corr + rs;
            m[r] = mn;
            o0[r] *= corr; o1[r] *= corr;
            s[r][0] = p0; s[r][1] = p1;
        }
        __syncthreads();
#pragma unroll
        for (int r = 0; r < 8; r++)
            *(float2*)&KPs[(qr + r) * AT_PAD + 2 * lane] = make_float2(s[r][0], s[r][1]);
        __syncthreads();
        const float* vr0 = &Vs[lane * AT_PAD];
        const float* vr1 = &Vs[(lane + 32) * AT_PAD];
#pragma unroll 4
        for (int k4 = 0; k4 < 16; k4++) {
            float4 v0 = *(const float4*)(vr0 + 4 * k4);
            float4 v1 = *(const float4*)(vr1 + 4 * k4);
#pragma unroll
            for (int r = 0; r < 8; r++) {
                float4 p = *(const float4*)&KPs[(qr + r) * AT_PAD + 4 * k4];
                o0[r] += p.x * v0.x + p.y * v0.y + p.z * v0.z + p.w * v0.w;
                o1[r] += p.x * v1.x + p.y * v1.y + p.z * v1.z + p.w * v1.w;
            }
        }
    }
#pragma unroll
    for (int r = 0; r < 8; r++) {
        float inv = 1.0f / l[r];
        int t = b * Sd + q0 + qr + r;
        float va = o0[r] * inv, vb = o1[r] * inv;
        __nv_bfloat16 ha = __float2bfloat16(va);
        __nv_bfloat16 la = __float2bfloat16(va - __bfloat162float(ha));
        __nv_bfloat16 hb = __float2bfloat16(vb);
        __nv_bfloat16 lb = __float2bfloat16(vb - __bfloat162float(hb));
        __nv_bfloat16* dp = g_attno3 + (size_t)t * 1024 + h * HDd + lane;
        dp[0] = ha; dp[32] = hb;
        dp[512] = la; dp[544] = lb;
    }
}

// ---------------- fused dual LN ----------------
__global__ void ln_k(const float* __restrict__ x,
                     const float* __restrict__ ln1w, const float* __restrict__ ln1b,
                     const float* __restrict__ ln2w, const float* __restrict__ ln2b,
                     float* __restrict__ out) {
    int t = blockIdx.x, tid = threadIdx.x;
    __shared__ float r1[8], r2[8];
    __shared__ float mu_s, rs_s;
    size_t off = (size_t)t * Dm;
    float a0 = x[off + tid] + g_attnout[off + tid];
    float a1 = x[off + 256 + tid] + g_attnout[off + 256 + tid];
    float s = a0 + a1, ss = a0 * a0 + a1 * a1;
#pragma unroll
    for (int o = 16; o; o >>= 1) {
        s += __shfl_xor_sync(0xffffffffu, s, o);
        ss += __shfl_xor_sync(0xffffffffu, ss, o);
    }
    if ((tid & 31) == 0) { r1[tid >> 5] = s; r2[tid >> 5] = ss; }
    __syncthreads();
    if (tid == 0) {
        float S = 0.f, SS = 0.f;
#pragma unroll
        for (int i = 0; i < 8; i++) { S += r1[i]; SS += r2[i]; }
        float mu = S * (1.0f / 512.0f);
        mu_s = mu;
        rs_s = rsqrtf(SS * (1.0f / 512.0f) - mu * mu + 1e-5f);
    }
    __syncthreads();
    float mu = mu_s, rs = rs_s;
    float z0 = (a0 - mu) * rs * ln1w[tid] + ln1b[tid] + g_nout[off + tid];
    float z1 = (a1 - mu) * rs * ln1w[256 + tid] + ln1b[256 + tid] + g_nout[off + 256 + tid];
    s = z0 + z1; ss = z0 * z0 + z1 * z1;
#pragma unroll
    for (int o = 16; o; o >>= 1) {
        s += __shfl_xor_sync(0xffffffffu, s, o);
        ss += __shfl_xor_sync(0xffffffffu, ss, o);
    }
    __syncthreads();
    if ((tid & 31) == 0) { r1[tid >> 5] = s; r2[tid >> 5] = ss; }
    __syncthreads();
    if (tid == 0) {
        float S = 0.f, SS = 0.f;
#pragma unroll
        for (int i = 0; i < 8; i++) { S += r1[i]; SS += r2[i]; }
        float mu2 = S * (1.0f / 512.0f);
        mu_s = mu2;
        rs_s = rsqrtf(SS * (1.0f / 512.0f) - mu2 * mu2 + 1e-5f);
    }
    __syncthreads();
    mu = mu_s; rs = rs_s;
    out[off + tid] = (z0 - mu) * rs * ln2w[tid] + ln2b[tid];
    out[off + 256 + tid] = (z1 - mu) * rs * ln2w[256 + tid] + ln2b[256 + tid];
}

// ---------------- launcher ----------------
extern "C" void kernel_launch(void* const* d_in, const int* in_sizes, int n_in,
                              void* d_out, int out_size) {
    const float* x    = (const float*)d_in[0];
    const float* Wr   = (const float*)d_in[1];
    const float* br   = (const float*)d_in[2];
    const float* W1   = (const float*)d_in[3];
    const float* b1   = (const float*)d_in[4];
    const float* W2   = (const float*)d_in[5];
    const float* b2   = (const float*)d_in[6];
    const float* Wqkv = (const float*)d_in[7];
    const float* bqkv = (const float*)d_in[8];
    const float* Wo   = (const float*)d_in[9];
    const float* bo   = (const float*)d_in[10];
    const float* ln1w = (const float*)d_in[11];
    const float* ln1b = (const float*)d_in[12];
    const float* ln2w = (const float*)d_in[13];
    const float* ln2b = (const float*)d_in[14];
    float* out = (float*)d_out;

    float *p_qkv, *p_attnout;
    __nv_bfloat16 *p_x3, *p_w13, *p_w23, *p_wqkv3, *p_wo3, *p_nout3, *p_attno3;
    cudaGetSymbolAddress((void**)&p_qkv, g_qkv);
    cudaGetSymbolAddress((void**)&p_attnout, g_attnout);
    cudaGetSymbolAddress((void**)&p_x3, g_x3);
    cudaGetSymbolAddress((void**)&p_w13, g_W13);
    cudaGetSymbolAddress((void**)&p_w23, g_W23);
    cudaGetSymbolAddress((void**)&p_wqkv3, g_Wqkv3);
    cudaGetSymbolAddress((void**)&p_wo3, g_Wo3);
    cudaGetSymbolAddress((void**)&p_nout3, g_nout3);
    cudaGetSymbolAddress((void**)&p_attno3, g_attno3);

    static int init_done = 0;
    static cudaStream_t sA, sB;
    static cudaEvent_t evRoot, evA, evB, evQ, evO;
    if (!init_done) {
        cudaFuncSetAttribute(attn2_k, cudaFuncAttributeMaxDynamicSharedMemorySize, SMEM_ATTN);
        cudaFuncSetAttribute(ffn1_mma_k, cudaFuncAttributeMaxDynamicSharedMemorySize, SMEM_FFN);
        cudaFuncSetAttribute(ffn2_mma_k, cudaFuncAttributeMaxDynamicSharedMemorySize, SMEM_FFN);
        cudaFuncSetAttribute(gemm_mma_k, cudaFuncAttributeMaxDynamicSharedMemorySize, SMEM_FFN);
        cudaStreamCreateWithFlags(&sA, cudaStreamNonBlocking);
        cudaStreamCreateWithFlags(&sB, cudaStreamNonBlocking);
        cudaEventCreateWithFlags(&evRoot, cudaEventDisableTiming);
        cudaEventCreateWithFlags(&evA, cudaEventDisableTiming);
        cudaEventCreateWithFlags(&evB, cudaEventDisableTiming);
        cudaEventCreateWithFlags(&evQ, cudaEventDisableTiming);
        cudaEventCreateWithFlags(&evO, cudaEventDisableTiming);
        init_done = 1;
    }

    // fork point
    cudaEventRecord(evRoot, 0);
    cudaStreamWaitEvent(sA, evRoot, 0);
    cudaStreamWaitEvent(sB, evRoot, 0);

    // stream A: inputs needed by ffn1
    conv3_k<<<T * Dm / 256, 256, 0, sA>>>(x, p_x3);
    convw_k<<<dim3(Hd / 32, Dm / 32, Np), dim3(32, 8), 0, sA>>>(W1, p_w13, Dm, Hd);
    cudaEventRecord(evA, sA);

    // stream B: inputs needed by ffn2 / projections
    convw_k<<<dim3(Dm / 32, Hd / 32, Np), dim3(32, 8), 0, sB>>>(W2, p_w23, Hd, Dm);
    cudaEventRecord(evB, sB);
    convwd_k<<<D3 * Dm / 256, 256, 0, sB>>>(Wqkv, p_wqkv3, Dm);
    cudaEventRecord(evQ, sB);
    convwd_k<<<Dm * Dm / 256, 256, 0, sB>>>(Wo, p_wo3, Dm);
    cudaEventRecord(evO, sB);

    // main stream: router + list build (overlaps conversions)
    router_k<<<T / 8, 256>>>(x, Wr, br);
    zero_k<<<1, 32>>>();
    build_k<<<(T * Kk + 255) / 256, 256>>>();

    // sparse FFN on tensor cores
    cudaStreamWaitEvent(0, evA, 0);
    ffn1_mma_k<<<dim3(16, 16, 32), 256, SMEM_FFN>>>(b1);
    cudaStreamWaitEvent(0, evB, 0);
    ffn2_mma_k<<<dim3(4, 16, 32), 256, SMEM_FFN>>>(b2);
    reduce3_k<<<(T * Dm / 4 + 255) / 256, 256>>>();

    // attention (HMMA projections + fp32 flash core)
    cudaStreamWaitEvent(0, evQ, 0);
    gemm_mma_k<<<dim3(D3 / 128, T / 128), 256, SMEM_FFN>>>(p_nout3, p_wqkv3, bqkv, p_qkv, D3, Dm);
    attn2_k<<<dim3(Sd / 64, NHd, Bd), 256, SMEM_ATTN>>>();
    cudaStreamWaitEvent(0, evO, 0);
    gemm_mma_k<<<dim3(Dm / 128, T / 128), 256, SMEM_FFN>>>(p_attno3, p_wo3, bo, p_attnout, Dm, Dm);

    // epilogue
    ln_k<<<T, 256>>>(x, ln1w, ln1b, ln2w, ln2b, out);
}